// round 4
// baseline (speedup 1.0000x reference)
#include <cuda_runtime.h>
#include <cuda_bf16.h>
#include <math.h>

#define T_STEPS 16384
#define N_DIM   256
#define M_DIM   512
#define G3      1536   // 3*M
#define NADDR   512    // K_MEM+1
#define L_OUT   256

// ---------------- device scratch (static, no allocation) ----------------
__device__ float d_Gi[T_STEPS * G3];     // X @ W_ih^T + b_ih
__device__ float d_H [T_STEPS * M_DIM];  // h_out history
__device__ float d_M [NADDR * M_DIM];    // memory rows (never read before written)

// ---------------- textbook 32x32 tiled NT GEMM ----------------
// C[m,n] = sum_k A[m*K+k] * B[n*K+k] + bias[n]
// block = (32,32): tx -> n (fast), ty -> m. All dims divide 32.
__global__ __launch_bounds__(1024) void gemm32_nt(
    const float* __restrict__ A, const float* __restrict__ B,
    const float* __restrict__ bias, float* __restrict__ C,
    int M, int N, int K)
{
    __shared__ float As[32][33];
    __shared__ float Bs[32][33];
    const int bm = blockIdx.y * 32;
    const int bn = blockIdx.x * 32;
    const int tx = threadIdx.x;
    const int ty = threadIdx.y;
    float acc = 0.f;
    for (int k0 = 0; k0 < K; k0 += 32) {
        As[ty][tx] = A[(size_t)(bm + ty) * K + k0 + tx];
        Bs[ty][tx] = B[(size_t)(bn + ty) * K + k0 + tx];
        __syncthreads();
        #pragma unroll
        for (int k = 0; k < 32; k++)
            acc = fmaf(As[ty][k], Bs[tx][k], acc);
        __syncthreads();
    }
    C[(size_t)(bm + ty) * N + bn + tx] = acc + bias[bn + tx];
}

// ---------------- single-CTA sequential recurrent kernel ----------------
// 1024 threads, one CTA. No cross-CTA communication at all.
__global__ __launch_bounds__(1024, 1) void dmm_seq(
    const float* __restrict__ h0,
    const float* __restrict__ W_hh,
    const float* __restrict__ b_hh,
    const float* __restrict__ C_w,
    const float* __restrict__ C_b)
{
    __shared__ float h_sm[M_DIM];
    __shared__ float hn_sm[M_DIM];
    __shared__ float gh_sm[G3];
    __shared__ float logit_sm[NADDR];
    __shared__ unsigned long long key_sm[NADDR];
    __shared__ unsigned char written_sm[NADDR];
    __shared__ int q_sm, has_sm;

    const int tid = threadIdx.x;
    const int w   = tid >> 5;
    const int l   = tid & 31;

    if (tid < M_DIM) { h_sm[tid] = h0[tid]; written_sm[tid] = 0; }
    __syncthreads();

    for (int t = 0; t < T_STEPS; t++) {
        // --- issue Gi loads early (latency overlaps GEMV) ---
        float gi0 = 0.f, gi1 = 0.f, gi2 = 0.f;
        if (tid < M_DIM) {
            const float* g = &d_Gi[(size_t)t * G3];
            gi0 = g[tid];
            gi1 = g[M_DIM + tid];
            gi2 = g[2 * M_DIM + tid];
        }

        // --- GEMV: gh = W_hh @ h  (1536 rows, warp per row, strided) ---
        for (int r = w; r < G3; r += 32) {
            const float4* Wr = (const float4*)&W_hh[(size_t)r * M_DIM];
            float acc = 0.f;
            #pragma unroll
            for (int cch = 0; cch < 4; cch++) {
                float4 wv = __ldg(&Wr[cch * 32 + l]);
                float4 hv = *(const float4*)&h_sm[cch * 128 + 4 * l];
                acc = fmaf(wv.x, hv.x, fmaf(wv.y, hv.y,
                      fmaf(wv.z, hv.z, fmaf(wv.w, hv.w, acc))));
            }
            #pragma unroll
            for (int o = 16; o > 0; o >>= 1)
                acc += __shfl_xor_sync(0xFFFFFFFFu, acc, o);
            if (l == 0) gh_sm[r] = acc;
        }
        __syncthreads();

        // --- gates (torch GRU semantics) ---
        if (tid < M_DIM) {
            float hr = gh_sm[tid]             + b_hh[tid];
            float hz = gh_sm[M_DIM + tid]     + b_hh[M_DIM + tid];
            float hn = gh_sm[2 * M_DIM + tid] + b_hh[2 * M_DIM + tid];
            float rg = 1.f / (1.f + expf(-(gi0 + hr)));
            float zg = 1.f / (1.f + expf(-(gi1 + hz)));
            float ng = tanhf(gi2 + rg * hn);
            hn_sm[tid] = (1.f - zg) * ng + zg * h_sm[tid];
        }
        __syncthreads();

        // --- logits = C_w @ h_new + C_b  (512 rows, warp per row, strided) ---
        for (int a = w; a < NADDR; a += 32) {
            const float4* Cr = (const float4*)&C_w[(size_t)a * M_DIM];
            float acc = 0.f;
            #pragma unroll
            for (int cch = 0; cch < 4; cch++) {
                float4 wv = __ldg(&Cr[cch * 32 + l]);
                float4 hv = *(const float4*)&hn_sm[cch * 128 + 4 * l];
                acc = fmaf(wv.x, hv.x, fmaf(wv.y, hv.y,
                      fmaf(wv.z, hv.z, fmaf(wv.w, hv.w, acc))));
            }
            #pragma unroll
            for (int o = 16; o > 0; o >>= 1)
                acc += __shfl_xor_sync(0xFFFFFFFFu, acc, o);
            if (l == 0) logit_sm[a] = acc + C_b[a];
        }
        __syncthreads();

        // --- argmax with first-index tie-break (matches jnp.argmax) ---
        if (tid < NADDR) {
            unsigned int u = __float_as_uint(logit_sm[tid]);
            u ^= (u & 0x80000000u) ? 0xFFFFFFFFu : 0x80000000u;
            key_sm[tid] = ((unsigned long long)u << 32) | (unsigned int)(1023 - tid);
        }
        __syncthreads();
        for (int s = NADDR / 2; s > 0; s >>= 1) {
            if (tid < s) {
                if (key_sm[tid + s] > key_sm[tid]) key_sm[tid] = key_sm[tid + s];
            }
            __syncthreads();
        }
        if (tid == 0) {
            int q   = 1023 - (int)(key_sm[0] & 0xFFFFFFFFull);
            int has = (q > 0) && (written_sm[q] != 0);
            if (q > 0) written_sm[q] = 1;
            q_sm = q; has_sm = has;
        }
        __syncthreads();
        const int q = q_sm, has = has_sm;

        // --- memory op + state update + history ---
        if (tid < M_DIM) {
            float hout;
            if (has) {
                hout = d_M[(size_t)q * M_DIM + tid];      // read stored row
            } else {
                hout = hn_sm[tid];
                if (q > 0) d_M[(size_t)q * M_DIM + tid] = hout;  // first write
            }
            h_sm[tid] = hout;
            d_H[(size_t)t * M_DIM + tid] = hout;
        }
        __syncthreads();
    }
}

extern "C" void kernel_launch(void* const* d_in, const int* in_sizes, int n_in,
                              void* d_out, int out_size)
{
    const float* X    = (const float*)d_in[0];
    const float* h0   = (const float*)d_in[1];
    const float* W_ih = (const float*)d_in[2];
    const float* W_hh = (const float*)d_in[3];
    const float* b_ih = (const float*)d_in[4];
    const float* b_hh = (const float*)d_in[5];
    const float* C_w  = (const float*)d_in[6];
    const float* C_b  = (const float*)d_in[7];
    const float* V_w  = (const float*)d_in[8];
    const float* V_b  = (const float*)d_in[9];
    float* Y = (float*)d_out;

    float* Gi; cudaGetSymbolAddress((void**)&Gi, d_Gi);
    float* H;  cudaGetSymbolAddress((void**)&H,  d_H);

    // 1) Gi = X @ W_ih^T + b_ih   [16384 x 1536]
    {
        dim3 blk(32, 32), grid(G3 / 32, T_STEPS / 32);
        gemm32_nt<<<grid, blk>>>(X, W_ih, b_ih, Gi, T_STEPS, G3, N_DIM);
    }
    // 2) sequential recurrent loop (single CTA — bisection-grade simplicity)
    dmm_seq<<<1, 1024>>>(h0, W_hh, b_hh, C_w, C_b);
    // 3) Y = H @ V_w^T + V_b   [16384 x 256]
    {
        dim3 blk(32, 32), grid(L_OUT / 32, T_STEPS / 32);
        gemm32_nt<<<grid, blk>>>(H, V_w, V_b, Y, T_STEPS, L_OUT, M_DIM);
    }
}

// round 6
// speedup vs baseline: 9.8259x; 9.8259x over previous
#include <cuda_runtime.h>
#include <cuda_bf16.h>
#include <math.h>

#define T_STEPS 16384
#define N_DIM   256
#define M_DIM   512
#define G3      1536   // 3*M
#define NADDR   512    // K_MEM+1
#define L_OUT   256

#define CSZ     16     // cluster size (CTAs)
#define DPC     32     // h-dims per CTA (512/16)
#define NTHR    512

// ---------------- device scratch (static, no allocation) ----------------
__device__ __align__(16) float d_Gi[T_STEPS * G3];     // X @ W_ih^T + b_ih
__device__ __align__(16) float d_H [T_STEPS * M_DIM];  // h_out history
__device__ __align__(16) float d_M [NADDR * M_DIM];    // memory rows

// ---------------- helpers ----------------
__device__ __forceinline__ float ldcg_f(const float* p) {
    float v; asm volatile("ld.global.cg.f32 %0, [%1];" : "=f"(v) : "l"(p) : "memory"); return v;
}
__device__ __forceinline__ void stcg_f(float* p, float v) {
    asm volatile("st.global.cg.f32 [%0], %1;" :: "l"(p), "f"(v) : "memory");
}
__device__ __forceinline__ void dsmem_st_f32(float* localPtr, unsigned rank, float v) {
    unsigned laddr = (unsigned)__cvta_generic_to_shared(localPtr);
    unsigned raddr;
    asm volatile("mapa.shared::cluster.u32 %0, %1, %2;" : "=r"(raddr) : "r"(laddr), "r"(rank));
    asm volatile("st.shared::cluster.f32 [%0], %1;" :: "r"(raddr), "f"(v) : "memory");
}
__device__ __forceinline__ void dsmem_st_u64(unsigned long long* localPtr, unsigned rank,
                                             unsigned long long v) {
    unsigned laddr = (unsigned)__cvta_generic_to_shared(localPtr);
    unsigned raddr;
    asm volatile("mapa.shared::cluster.u32 %0, %1, %2;" : "=r"(raddr) : "r"(laddr), "r"(rank));
    asm volatile("st.shared::cluster.u64 [%0], %1;" :: "r"(raddr), "l"(v) : "memory");
}
#define CLUSTER_SYNC() do { \
    asm volatile("barrier.cluster.arrive.aligned;" ::: "memory"); \
    asm volatile("barrier.cluster.wait.aligned;"   ::: "memory"); } while (0)

// ---------------- textbook 32x32 tiled NT GEMM (known good, round 4) ----------------
__global__ __launch_bounds__(1024) void gemm32_nt(
    const float* __restrict__ A, const float* __restrict__ B,
    const float* __restrict__ bias, float* __restrict__ C,
    int M, int N, int K)
{
    __shared__ float As[32][33];
    __shared__ float Bs[32][33];
    const int bm = blockIdx.y * 32;
    const int bn = blockIdx.x * 32;
    const int tx = threadIdx.x;
    const int ty = threadIdx.y;
    float acc = 0.f;
    for (int k0 = 0; k0 < K; k0 += 32) {
        As[ty][tx] = A[(size_t)(bm + ty) * K + k0 + tx];
        Bs[ty][tx] = B[(size_t)(bn + ty) * K + k0 + tx];
        __syncthreads();
        #pragma unroll
        for (int k = 0; k < 32; k++)
            acc = fmaf(As[ty][k], Bs[tx][k], acc);
        __syncthreads();
    }
    C[(size_t)(bm + ty) * N + bn + tx] = acc + bias[bn + tx];
}

// ---------------- clustered recurrent kernel ----------------
// One 16-CTA cluster. CTA c owns h-dims [32c, 32c+32); warp w owns dims
// d0=32c+w, d1=32c+16+w (3 GEMV rows each, weights in SMEM) and logit
// addresses d0,d1 (C_w rows in registers). Exchange via DSMEM + cluster.sync.
// Every dot/gate/key is the verbatim round-4 computation (bit-identical).
__global__ __launch_bounds__(NTHR, 1) void dmm_rec(
    const float* __restrict__ h0,
    const float* __restrict__ W_hh,
    const float* __restrict__ b_hh,
    const float* __restrict__ C_w,
    const float* __restrict__ C_b)
{
    extern __shared__ float W_sm[];               // [3*DPC][512] gate-major
    __shared__ float h_sm[M_DIM];
    __shared__ float hn_sm[2][M_DIM];             // double-buffered h_new (DSMEM target)
    __shared__ unsigned long long wkey_sm[16];
    __shared__ unsigned long long ckey_sm[CSZ];   // per-CTA keys (DSMEM target)
    __shared__ unsigned char written_sm[NADDR];
    __shared__ int dec_sm;

    const int c   = blockIdx.x;                   // == cluster_ctarank (single cluster)
    const int tid = threadIdx.x;
    const int w   = tid >> 5;
    const int l   = tid & 31;
    const int d0  = DPC * c + w;
    const int d1  = DPC * c + 16 + w;
    const int myd = (l < 16) ? d0 : d1;

    // ---- one-time: W_hh slice -> SMEM (gate-major), state init ----
    for (int idx = tid; idx < 3 * DPC * M_DIM; idx += NTHR) {
        int g   = idx >> 14;          // / (32*512)
        int rem = idx & 16383;
        int lr  = rem >> 9;
        int col = rem & 511;
        W_sm[idx] = W_hh[(size_t)(g * M_DIM + DPC * c + lr) * M_DIM + col];
    }
    h_sm[tid] = h0[tid];
    written_sm[tid] = 0;

    float4 cw0[4], cw1[4];
    #pragma unroll
    for (int cch = 0; cch < 4; cch++) {
        cw0[cch] = *(const float4*)&C_w[(size_t)d0 * M_DIM + cch * 128 + 4 * l];
        cw1[cch] = *(const float4*)&C_w[(size_t)d1 * M_DIM + cch * 128 + 4 * l];
    }
    const float cb0 = C_b[d0], cb1 = C_b[d1];
    const float bhr = b_hh[myd], bhz = b_hh[M_DIM + myd], bhn = b_hh[2 * M_DIM + myd];

    __syncthreads();
    CLUSTER_SYNC();

    for (int t = 0; t < T_STEPS; t++) {
        const int tb = t & 1;

        // ---- gi for this step (lanes 0,16 compute gates) ----
        float gir = 0.f, giz = 0.f, gin = 0.f;
        if ((l & 15) == 0) {
            const float* g = &d_Gi[(size_t)t * G3];
            gir = __ldg(&g[myd]);
            giz = __ldg(&g[M_DIM + myd]);
            gin = __ldg(&g[2 * M_DIM + myd]);
        }
        const float hprev = h_sm[myd];

        // ---- h into registers once, reused for all 6 dots ----
        float4 hv[4];
        #pragma unroll
        for (int cch = 0; cch < 4; cch++) hv[cch] = *(const float4*)&h_sm[cch * 128 + 4 * l];

        // ---- 6 GEMV dots (verbatim round-4 chain + reduce) ----
        auto dot = [&](const float* __restrict__ row) -> float {
            float acc = 0.f;
            #pragma unroll
            for (int cch = 0; cch < 4; cch++) {
                float4 wv = *(const float4*)&row[cch * 128 + 4 * l];
                acc = fmaf(wv.x, hv[cch].x, fmaf(wv.y, hv[cch].y,
                      fmaf(wv.z, hv[cch].z, fmaf(wv.w, hv[cch].w, acc))));
            }
            #pragma unroll
            for (int o = 16; o > 0; o >>= 1) acc += __shfl_xor_sync(0xFFFFFFFFu, acc, o);
            return acc;
        };
        const float a0r = dot(&W_sm[(0 * DPC + w)      * M_DIM]);
        const float a0z = dot(&W_sm[(1 * DPC + w)      * M_DIM]);
        const float a0n = dot(&W_sm[(2 * DPC + w)      * M_DIM]);
        const float a1r = dot(&W_sm[(0 * DPC + 16 + w) * M_DIM]);
        const float a1z = dot(&W_sm[(1 * DPC + 16 + w) * M_DIM]);
        const float a1n = dot(&W_sm[(2 * DPC + 16 + w) * M_DIM]);

        // ---- gates (verbatim round-4 expressions) on lanes 0 and 16 ----
        float hnewv = 0.f;
        if (l == 0) {
            float hr = a0r + bhr, hz = a0z + bhz, hn = a0n + bhn;
            float rg = 1.f / (1.f + expf(-(gir + hr)));
            float zg = 1.f / (1.f + expf(-(giz + hz)));
            float ng = tanhf(gin + rg * hn);
            hnewv = (1.f - zg) * ng + zg * hprev;
        } else if (l == 16) {
            float hr = a1r + bhr, hz = a1z + bhz, hn = a1n + bhn;
            float rg = 1.f / (1.f + expf(-(gir + hr)));
            float zg = 1.f / (1.f + expf(-(giz + hz)));
            float ng = tanhf(gin + rg * hn);
            hnewv = (1.f - zg) * ng + zg * hprev;
        }
        const float v0 = __shfl_sync(0xFFFFFFFFu, hnewv, 0);
        const float v1 = __shfl_sync(0xFFFFFFFFu, hnewv, 16);

        // ---- broadcast h_new to every CTA's hn_sm via DSMEM ----
        {
            unsigned dstRank = (unsigned)(l & 15);
            float    val     = (l < 16) ? v0 : v1;
            int      dstDim  = (l < 16) ? d0 : d1;
            dsmem_st_f32(&hn_sm[tb][dstDim], dstRank, val);
        }
        CLUSTER_SYNC();   // sync #1: hn_sm complete everywhere

        // ---- logits for addresses d0,d1 (verbatim chain + reduce) ----
        float4 nv[4];
        #pragma unroll
        for (int cch = 0; cch < 4; cch++) nv[cch] = *(const float4*)&hn_sm[tb][cch * 128 + 4 * l];
        float acc0 = 0.f, acc1 = 0.f;
        #pragma unroll
        for (int cch = 0; cch < 4; cch++) {
            acc0 = fmaf(cw0[cch].x, nv[cch].x, fmaf(cw0[cch].y, nv[cch].y,
                   fmaf(cw0[cch].z, nv[cch].z, fmaf(cw0[cch].w, nv[cch].w, acc0))));
        }
        #pragma unroll
        for (int o = 16; o > 0; o >>= 1) acc0 += __shfl_xor_sync(0xFFFFFFFFu, acc0, o);
        #pragma unroll
        for (int cch = 0; cch < 4; cch++) {
            acc1 = fmaf(cw1[cch].x, nv[cch].x, fmaf(cw1[cch].y, nv[cch].y,
                   fmaf(cw1[cch].z, nv[cch].z, fmaf(cw1[cch].w, nv[cch].w, acc1))));
        }
        #pragma unroll
        for (int o = 16; o > 0; o >>= 1) acc1 += __shfl_xor_sync(0xFFFFFFFFu, acc1, o);

        if (l == 0) {
            float lg0 = acc0 + cb0;
            unsigned int u0 = __float_as_uint(lg0);
            u0 ^= (u0 & 0x80000000u) ? 0xFFFFFFFFu : 0x80000000u;
            unsigned long long k0 = ((unsigned long long)u0 << 32) | (unsigned int)(1023 - d0);
            float lg1 = acc1 + cb1;
            unsigned int u1 = __float_as_uint(lg1);
            u1 ^= (u1 & 0x80000000u) ? 0xFFFFFFFFu : 0x80000000u;
            unsigned long long k1 = ((unsigned long long)u1 << 32) | (unsigned int)(1023 - d1);
            wkey_sm[w] = (k0 > k1) ? k0 : k1;
        }
        __syncthreads();

        // ---- CTA key -> every CTA's ckey_sm[c] via DSMEM ----
        if (w == 0) {
            unsigned long long k = (l < 16) ? wkey_sm[l] : 0ull;
            #pragma unroll
            for (int o = 16; o > 0; o >>= 1) {
                unsigned long long ok = __shfl_xor_sync(0xFFFFFFFFu, k, o);
                if (ok > k) k = ok;
            }
            if (l < CSZ) dsmem_st_u64(&ckey_sm[c], (unsigned)l, k);
        }
        CLUSTER_SYNC();   // sync #2: all 16 CTA keys visible everywhere

        // ---- redundant decision (identical in every CTA) ----
        if (w == 0) {
            unsigned long long k = (l < CSZ) ? ckey_sm[l] : 0ull;
            #pragma unroll
            for (int o = 16; o > 0; o >>= 1) {
                unsigned long long ok = __shfl_xor_sync(0xFFFFFFFFu, k, o);
                if (ok > k) k = ok;
            }
            if (l == 0) {
                int q   = 1023 - (int)(k & 0xFFFFFFFFull);
                int has = (q > 0) && (written_sm[q] != 0);
                if (q > 0) written_sm[q] = 1;
                dec_sm = (q << 1) | has;
            }
        }
        __syncthreads();
        const int dec = dec_sm;
        const int q   = dec >> 1;
        const int has = dec & 1;

        // ---- memory op + state update + history (all local/replicated) ----
        float hout;
        if (has) {
            hout = ldcg_f(&d_M[(size_t)q * M_DIM + tid]);
        } else {
            hout = hn_sm[tb][tid];
            if (q > 0 && c == (q & (CSZ - 1)))
                stcg_f(&d_M[(size_t)q * M_DIM + tid], hout);
        }
        h_sm[tid] = hout;
        if (c == 0) d_H[(size_t)t * M_DIM + tid] = hout;
        __syncthreads();
    }
}

extern "C" void kernel_launch(void* const* d_in, const int* in_sizes, int n_in,
                              void* d_out, int out_size)
{
    const float* X    = (const float*)d_in[0];
    const float* h0   = (const float*)d_in[1];
    const float* W_ih = (const float*)d_in[2];
    const float* W_hh = (const float*)d_in[3];
    const float* b_ih = (const float*)d_in[4];
    const float* b_hh = (const float*)d_in[5];
    const float* C_w  = (const float*)d_in[6];
    const float* C_b  = (const float*)d_in[7];
    const float* V_w  = (const float*)d_in[8];
    const float* V_b  = (const float*)d_in[9];
    float* Y = (float*)d_out;

    float* Gi; cudaGetSymbolAddress((void**)&Gi, d_Gi);
    float* H;  cudaGetSymbolAddress((void**)&H,  d_H);

    // 1) Gi = X @ W_ih^T + b_ih
    {
        dim3 blk(32, 32), grid(G3 / 32, T_STEPS / 32);
        gemm32_nt<<<grid, blk>>>(X, W_ih, b_ih, Gi, T_STEPS, G3, N_DIM);
    }
    // 2) clustered recurrent loop (one 16-CTA cluster, HW barriers)
    {
        const int smem = 3 * DPC * M_DIM * (int)sizeof(float);   // 196608
        static int configured = 0;
        if (!configured) {
            cudaFuncSetAttribute(dmm_rec, cudaFuncAttributeNonPortableClusterSizeAllowed, 1);
            cudaFuncSetAttribute(dmm_rec, cudaFuncAttributeMaxDynamicSharedMemorySize, smem);
            configured = 1;
        }
        cudaLaunchConfig_t cfg = {};
        cfg.gridDim  = dim3(CSZ, 1, 1);
        cfg.blockDim = dim3(NTHR, 1, 1);
        cfg.dynamicSmemBytes = smem;
        cfg.stream = 0;
        cudaLaunchAttribute at[1];
        at[0].id = cudaLaunchAttributeClusterDimension;
        at[0].val.clusterDim.x = CSZ;
        at[0].val.clusterDim.y = 1;
        at[0].val.clusterDim.z = 1;
        cfg.attrs = at;
        cfg.numAttrs = 1;
        cudaLaunchKernelEx(&cfg, dmm_rec, h0, W_hh, b_hh, C_w, C_b);
    }
    // 3) Y = H @ V_w^T + V_b
    {
        dim3 blk(32, 32), grid(L_OUT / 32, T_STEPS / 32);
        gemm32_nt<<<grid, blk>>>(H, V_w, V_b, Y, T_STEPS, L_OUT, M_DIM);
    }
}